// round 3
// baseline (speedup 1.0000x reference)
#include <cuda_runtime.h>
#include <cuda_fp16.h>
#include <cstdint>

// ---------------------------------------------------------------------------
// Problem constants
// ---------------------------------------------------------------------------
#define BATCH   2
#define NRES    1280
#define KNBR    48
#define C_NODE  384
#define C_EDGE  128
#define C_OUT_  128
#define C_BIAS  192
#define HID     512
#define NODES   (BATCH * NRES)        // 2560
#define MROWS   (NODES * KNBR)        // 122880

// ---------------------------------------------------------------------------
// Scratch (static device globals; allocation-free per harness rules)
// ---------------------------------------------------------------------------
__device__ float  g_n[NODES * C_BIAS];                       // node projection (fp32)
__device__ __half g_X [(size_t)MROWS * HID];                 // concat input rows
__device__ __half g_H [(size_t)MROWS * HID];                 // relu(x@W1+b1)
__device__ __half g_H2[(size_t)MROWS * HID];                 // relu(h@W2+b2)
__device__ float  g_Y [(size_t)MROWS * C_OUT_];              // pre-LN output
__device__ __half g_W1h[HID * HID];
__device__ __half g_W2h[HID * HID];
__device__ __half g_Wfh[HID * C_OUT_];

// ---------------------------------------------------------------------------
// fp32 -> fp16 weight conversion
// ---------------------------------------------------------------------------
__global__ void f2h_kernel(const float* __restrict__ src, __half* __restrict__ dst, int n) {
    for (int i = blockIdx.x * blockDim.x + threadIdx.x; i < n; i += gridDim.x * blockDim.x)
        dst[i] = __float2half_rn(src[i]);
}

// ---------------------------------------------------------------------------
// n = node_emb @ Wi + bi      [2560,384] @ [384,192]  (fp32)
// One block = 16 rows x 192 cols; 192 threads, thread j owns column j of 16 rows.
// ---------------------------------------------------------------------------
__global__ void node_proj_kernel(const float* __restrict__ node,
                                 const float* __restrict__ Wi,
                                 const float* __restrict__ bi) {
    __shared__ float s[16 * C_NODE];
    const int t  = threadIdx.x;          // 0..191
    const int r0 = blockIdx.x * 16;
    for (int idx = t; idx < 16 * C_NODE; idx += 192)
        s[idx] = node[(size_t)r0 * C_NODE + idx];
    __syncthreads();

    float acc[16];
#pragma unroll
    for (int r = 0; r < 16; r++) acc[r] = 0.f;

    const int j = t;
    for (int k4 = 0; k4 < C_NODE / 4; k4++) {
        const float w0 = Wi[(k4 * 4 + 0) * C_BIAS + j];
        const float w1 = Wi[(k4 * 4 + 1) * C_BIAS + j];
        const float w2 = Wi[(k4 * 4 + 2) * C_BIAS + j];
        const float w3 = Wi[(k4 * 4 + 3) * C_BIAS + j];
#pragma unroll
        for (int r = 0; r < 16; r++) {
            const float4 sv = *reinterpret_cast<const float4*>(&s[r * C_NODE + k4 * 4]);
            acc[r] += sv.x * w0 + sv.y * w1 + sv.z * w2 + sv.w * w3;
        }
    }
    const float bv = bi[j];
#pragma unroll
    for (int r = 0; r < 16; r++)
        g_n[(size_t)(r0 + r) * C_BIAS + j] = acc[r] + bv;
}

// ---------------------------------------------------------------------------
// Build X[b,i,k] = concat(edge[b,i,k] (128), n[b,i] (192), n[b,E_idx[b,i,k]] (192))
// One block per (b,i); 256 threads.
// ---------------------------------------------------------------------------
__global__ void build_x_kernel(const float* __restrict__ edge, const int* __restrict__ Eidx) {
    const int bi = blockIdx.x;           // b*NRES + i
    __shared__ __half s_self[C_BIAS];
    __shared__ int    s_idx[KNBR];
    const int t = threadIdx.x;
    if (t < C_BIAS) s_self[t] = __float2half_rn(g_n[(size_t)bi * C_BIAS + t]);
    if (t < KNBR)   s_idx[t]  = Eidx[bi * KNBR + t];
    __syncthreads();

    const int b = bi / NRES;
    const float* nb = g_n + (size_t)b * NRES * C_BIAS;
    const float* er = edge + (size_t)bi * KNBR * C_EDGE;
    __half* xr = g_X + (size_t)bi * KNBR * HID;

    for (int idx = t; idx < KNBR * HID; idx += 256) {
        const int k = idx >> 9;          // / HID
        const int c = idx & (HID - 1);
        __half v;
        if (c < C_EDGE)                 v = __float2half_rn(er[k * C_EDGE + c]);
        else if (c < C_EDGE + C_BIAS)   v = s_self[c - C_EDGE];
        else v = __float2half_rn(nb[(size_t)s_idx[k] * C_BIAS + (c - C_EDGE - C_BIAS)]);
        xr[idx] = v;
    }
}

// ---------------------------------------------------------------------------
// GEMM: C[M, Nc] = act( A @ Bw + bias ),  K = 512 fixed (lda = 512), ldb = ldc = Nc.
// fp16 inputs, fp32 accumulate via mma.sync m16n8k16.
// BM=128, BN=128, BK=32; 256 threads (8 warps, 4x2), warp tile 32x64.
// Dual-A trick: KT=32 runs k-tiles 0..15 from A0 (=H2) and 16..31 from A1 (=X)
// against the SAME B rows -> computes (A0 + A1) @ Bw by linearity (residual).
// ---------------------------------------------------------------------------
template <bool RELU, bool OUT_HALF>
__global__ void __launch_bounds__(256, 2)
gemm_kernel(const __half* __restrict__ A0, const __half* __restrict__ A1,
            const __half* __restrict__ Bw, const float* __restrict__ bias,
            __half* __restrict__ Ch, float* __restrict__ Cf,
            int Nc, int KT) {
    const int BM = 128, BN = 128, BK = 32;
    __shared__ __half As[2][128][BK + 8];
    __shared__ __half Bs[2][BK][BN + 8];

    const int t = threadIdx.x, lane = t & 31, wid = t >> 5;
    const int bm = blockIdx.y, bn = blockIdx.x;
    const int wm = (wid >> 1) * 32, wn = (wid & 1) * 64;

    float acc[2][8][4];
#pragma unroll
    for (int a = 0; a < 2; a++)
#pragma unroll
        for (int b = 0; b < 8; b++)
#pragma unroll
            for (int c = 0; c < 4; c++) acc[a][b][c] = 0.f;

    auto load_tiles = [&](int st, int kt) {
        const __half* Ab = (kt < 16) ? A0 : A1;
        const int k0 = (kt & 15) * BK;
#pragma unroll
        for (int j = 0; j < 2; j++) {                 // A: 128 rows x 32 cols
            const int idx = j * 256 + t;
            const int r = idx >> 2, cc = idx & 3;
            const __half* src = Ab + ((size_t)bm * BM + r) * HID + k0 + cc * 8;
            const uint32_t dst = (uint32_t)__cvta_generic_to_shared(&As[st][r][cc * 8]);
            asm volatile("cp.async.cg.shared.global [%0], [%1], 16;\n" :: "r"(dst), "l"(src));
        }
#pragma unroll
        for (int j = 0; j < 2; j++) {                 // B: 32 rows x 128 cols
            const int idx = j * 256 + t;
            const int r = idx >> 4, cc = idx & 15;
            const __half* src = Bw + (size_t)(k0 + r) * Nc + bn * BN + cc * 8;
            const uint32_t dst = (uint32_t)__cvta_generic_to_shared(&Bs[st][r][cc * 8]);
            asm volatile("cp.async.cg.shared.global [%0], [%1], 16;\n" :: "r"(dst), "l"(src));
        }
    };

    load_tiles(0, 0);
    asm volatile("cp.async.commit_group;\n");

    for (int kt = 0; kt < KT; kt++) {
        if (kt + 1 < KT) {
            load_tiles((kt + 1) & 1, kt + 1);
            asm volatile("cp.async.commit_group;\n");
            asm volatile("cp.async.wait_group 1;\n");
        } else {
            asm volatile("cp.async.wait_group 0;\n");
        }
        __syncthreads();
        const int st = kt & 1;
#pragma unroll
        for (int kk = 0; kk < 2; kk++) {
            uint32_t afr[2][4];
#pragma unroll
            for (int mi = 0; mi < 2; mi++) {
                const uint32_t addr = (uint32_t)__cvta_generic_to_shared(
                    &As[st][wm + mi * 16 + (lane & 15)][kk * 16 + ((lane >> 4) << 3)]);
                asm volatile("ldmatrix.sync.aligned.m8n8.x4.shared.b16 {%0,%1,%2,%3}, [%4];\n"
                             : "=r"(afr[mi][0]), "=r"(afr[mi][1]), "=r"(afr[mi][2]), "=r"(afr[mi][3])
                             : "r"(addr));
            }
            uint32_t bfr[4][4];
#pragma unroll
            for (int nj = 0; nj < 4; nj++) {
                const uint32_t addr = (uint32_t)__cvta_generic_to_shared(
                    &Bs[st][kk * 16 + (lane & 15)][wn + nj * 16 + ((lane >> 4) << 3)]);
                asm volatile("ldmatrix.sync.aligned.m8n8.x4.trans.shared.b16 {%0,%1,%2,%3}, [%4];\n"
                             : "=r"(bfr[nj][0]), "=r"(bfr[nj][1]), "=r"(bfr[nj][2]), "=r"(bfr[nj][3])
                             : "r"(addr));
            }
#pragma unroll
            for (int mi = 0; mi < 2; mi++)
#pragma unroll
                for (int n8 = 0; n8 < 8; n8++) {
                    const uint32_t b0 = bfr[n8 >> 1][(n8 & 1) * 2 + 0];
                    const uint32_t b1 = bfr[n8 >> 1][(n8 & 1) * 2 + 1];
                    asm volatile(
                        "mma.sync.aligned.m16n8k16.row.col.f32.f16.f16.f32 "
                        "{%0,%1,%2,%3}, {%4,%5,%6,%7}, {%8,%9}, {%0,%1,%2,%3};\n"
                        : "+f"(acc[mi][n8][0]), "+f"(acc[mi][n8][1]),
                          "+f"(acc[mi][n8][2]), "+f"(acc[mi][n8][3])
                        : "r"(afr[mi][0]), "r"(afr[mi][1]), "r"(afr[mi][2]), "r"(afr[mi][3]),
                          "r"(b0), "r"(b1));
                }
        }
        __syncthreads();
    }

    // epilogue: +bias, optional relu, store half or fp32
    const int lr = lane >> 2, lc = (lane & 3) * 2;
#pragma unroll
    for (int mi = 0; mi < 2; mi++) {
#pragma unroll
        for (int n8 = 0; n8 < 8; n8++) {
            const int row = bm * BM + wm + mi * 16 + lr;
            const int col = bn * BN + wn + n8 * 8 + lc;
            const float bv0 = bias[col], bv1 = bias[col + 1];
            float v0 = acc[mi][n8][0] + bv0;
            float v1 = acc[mi][n8][1] + bv1;
            float v2 = acc[mi][n8][2] + bv0;
            float v3 = acc[mi][n8][3] + bv1;
            if (RELU) {
                v0 = fmaxf(v0, 0.f); v1 = fmaxf(v1, 0.f);
                v2 = fmaxf(v2, 0.f); v3 = fmaxf(v3, 0.f);
            }
            if (OUT_HALF) {
                *reinterpret_cast<__half2*>(Ch + (size_t)row * Nc + col)       = __floats2half2_rn(v0, v1);
                *reinterpret_cast<__half2*>(Ch + (size_t)(row + 8) * Nc + col) = __floats2half2_rn(v2, v3);
            } else {
                *reinterpret_cast<float2*>(Cf + (size_t)row * Nc + col)       = make_float2(v0, v1);
                *reinterpret_cast<float2*>(Cf + (size_t)(row + 8) * Nc + col) = make_float2(v2, v3);
            }
        }
    }
}

// ---------------------------------------------------------------------------
// LayerNorm over last dim (128): one warp per row, float4 per lane.
// ---------------------------------------------------------------------------
__global__ void ln_kernel(const float* __restrict__ Y, const float* __restrict__ gamma,
                          const float* __restrict__ beta, float* __restrict__ out) {
    const int row  = (blockIdx.x * blockDim.x + threadIdx.x) >> 5;
    const int lane = threadIdx.x & 31;
    const float4 v = reinterpret_cast<const float4*>(Y + (size_t)row * C_OUT_)[lane];
    float s  = v.x + v.y + v.z + v.w;
    float sq = v.x * v.x + v.y * v.y + v.z * v.z + v.w * v.w;
#pragma unroll
    for (int off = 16; off > 0; off >>= 1) {
        s  += __shfl_xor_sync(0xffffffffu, s, off);
        sq += __shfl_xor_sync(0xffffffffu, sq, off);
    }
    const float mu  = s * (1.f / C_OUT_);
    const float inv = rsqrtf(sq * (1.f / C_OUT_) - mu * mu + 1e-5f);
    const float4 gg = reinterpret_cast<const float4*>(gamma)[lane];
    const float4 bb = reinterpret_cast<const float4*>(beta)[lane];
    float4 o;
    o.x = (v.x - mu) * inv * gg.x + bb.x;
    o.y = (v.y - mu) * inv * gg.y + bb.y;
    o.z = (v.z - mu) * inv * gg.z + bb.z;
    o.w = (v.w - mu) * inv * gg.w + bb.w;
    reinterpret_cast<float4*>(out + (size_t)row * C_OUT_)[lane] = o;
}

// ---------------------------------------------------------------------------
// Launch
// ---------------------------------------------------------------------------
extern "C" void kernel_launch(void* const* d_in, const int* in_sizes, int n_in,
                              void* d_out, int out_size) {
    const float* node  = (const float*)d_in[0];
    const float* edge  = (const float*)d_in[1];
    const int*   eidx  = (const int*)  d_in[2];
    const float* Wi    = (const float*)d_in[3];
    const float* bi    = (const float*)d_in[4];
    const float* W1    = (const float*)d_in[5];
    const float* b1    = (const float*)d_in[6];
    const float* W2    = (const float*)d_in[7];
    const float* b2    = (const float*)d_in[8];
    const float* Wf    = (const float*)d_in[9];
    const float* bf    = (const float*)d_in[10];
    const float* gamma = (const float*)d_in[11];
    const float* beta  = (const float*)d_in[12];
    float* out = (float*)d_out;

    void *pW1h, *pW2h, *pWfh, *pX, *pH, *pH2, *pY;
    cudaGetSymbolAddress(&pW1h, g_W1h);
    cudaGetSymbolAddress(&pW2h, g_W2h);
    cudaGetSymbolAddress(&pWfh, g_Wfh);
    cudaGetSymbolAddress(&pX,  g_X);
    cudaGetSymbolAddress(&pH,  g_H);
    cudaGetSymbolAddress(&pH2, g_H2);
    cudaGetSymbolAddress(&pY,  g_Y);

    f2h_kernel<<<512, 256>>>(W1, (__half*)pW1h, HID * HID);
    f2h_kernel<<<512, 256>>>(W2, (__half*)pW2h, HID * HID);
    f2h_kernel<<<256, 256>>>(Wf, (__half*)pWfh, HID * C_OUT_);

    node_proj_kernel<<<NODES / 16, C_BIAS>>>(node, Wi, bi);
    build_x_kernel<<<NODES, 256>>>(edge, eidx);

    // h = relu(X @ W1 + b1)
    gemm_kernel<true, true><<<dim3(HID / 128, MROWS / 128), 256>>>(
        (const __half*)pX, (const __half*)pX, (const __half*)pW1h, b1,
        (__half*)pH, nullptr, HID, 16);
    // h2 = relu(h @ W2 + b2)
    gemm_kernel<true, true><<<dim3(HID / 128, MROWS / 128), 256>>>(
        (const __half*)pH, (const __half*)pH, (const __half*)pW2h, b2,
        (__half*)pH2, nullptr, HID, 16);
    // y = (h2 + X) @ Wf + bf   (dual-A over 32 k-tiles, by linearity)
    gemm_kernel<false, false><<<dim3(1, MROWS / 128), 256>>>(
        (const __half*)pH2, (const __half*)pX, (const __half*)pWfh, bf,
        nullptr, (float*)pY, C_OUT_, 32);

    ln_kernel<<<MROWS / 8, 256>>>((const float*)pY, gamma, beta, out);
}

// round 5
// speedup vs baseline: 1.2530x; 1.2530x over previous
#include <cuda_runtime.h>
#include <cuda_fp16.h>
#include <cstdint>

// ---------------------------------------------------------------------------
// Problem constants
// ---------------------------------------------------------------------------
#define BATCH   2
#define NRES    1280
#define KNBR    48
#define C_NODE  384
#define C_EDGE  128
#define C_OUT_  128
#define C_BIAS  192
#define HID     512
#define NODES   (BATCH * NRES)        // 2560
#define MROWS   (NODES * KNBR)        // 122880 = 960 * 128

// ---------------------------------------------------------------------------
// Scratch (static device globals; allocation-free per harness rules)
// ---------------------------------------------------------------------------
__device__ float  g_n[NODES * C_BIAS];
__device__ __half g_X [(size_t)MROWS * HID];
__device__ __half g_H [(size_t)MROWS * HID];
__device__ __half g_H2[(size_t)MROWS * HID];
__device__ __half g_W1h[HID * HID];      // [K=512][N=512]
__device__ __half g_W2h[HID * HID];
__device__ __half g_Wfh[HID * C_OUT_];   // [K=512][N=128]

// ---------------------------------------------------------------------------
// fp32 -> fp16 weight conversion
// ---------------------------------------------------------------------------
__global__ void f2h_kernel(const float* __restrict__ src, __half* __restrict__ dst, int n) {
    for (int i = blockIdx.x * blockDim.x + threadIdx.x; i < n; i += gridDim.x * blockDim.x)
        dst[i] = __float2half_rn(src[i]);
}

// ---------------------------------------------------------------------------
// n = node_emb @ Wi + bi   [2560,384]@[384,192]; block = 2 rows x 192 cols,
// 384 threads, one output per thread. Grid = 1280 blocks (full chip).
// ---------------------------------------------------------------------------
__global__ void node_proj_kernel(const float* __restrict__ node,
                                 const float* __restrict__ Wi,
                                 const float* __restrict__ bi) {
    __shared__ float s[2 * C_NODE];
    const int t  = threadIdx.x;               // 0..383
    const int r0 = blockIdx.x * 2;
    for (int i = t; i < 2 * C_NODE; i += 384)
        s[i] = node[(size_t)r0 * C_NODE + i];
    __syncthreads();
    const int row = t / C_BIAS;
    const int j   = t - row * C_BIAS;
    const float* sr = s + row * C_NODE;
    float acc = 0.f;
#pragma unroll 8
    for (int k = 0; k < C_NODE; k++) acc += sr[k] * Wi[k * C_BIAS + j];
    g_n[(size_t)(r0 + row) * C_BIAS + j] = acc + bi[j];
}

// ---------------------------------------------------------------------------
// Build X[b,i,k] = concat(edge(128), n[b,i](192), n[b,E_idx](192)) as fp16.
// Vectorized: one 8-element segment (16B store) per thread-iteration; every
// segment lies entirely inside one source region (boundaries 128/320 are
// multiples of 8).
// ---------------------------------------------------------------------------
__global__ void build_x_kernel(const float* __restrict__ edge, const int* __restrict__ Eidx) {
    const int bi = blockIdx.x;
    __shared__ __align__(16) __half s_self[C_BIAS];
    __shared__ int s_idx[KNBR];
    const int t = threadIdx.x;
    if (t < C_BIAS) s_self[t] = __float2half_rn(g_n[(size_t)bi * C_BIAS + t]);
    if (t < KNBR)   s_idx[t]  = Eidx[bi * KNBR + t];
    __syncthreads();

    const int b = bi / NRES;
    const float* nb = g_n + (size_t)b * NRES * C_BIAS;
    const float* er = edge + (size_t)bi * KNBR * C_EDGE;
    __half* xr = g_X + (size_t)bi * KNBR * HID;

    // KNBR * (HID/8) = 48 * 64 = 3072 segments
    for (int g = t; g < KNBR * (HID / 8); g += 256) {
        const int k  = g >> 6;
        const int c8 = (g & 63) * 8;
        uint4 w;
        if (c8 < C_EDGE) {
            const float4 a = *reinterpret_cast<const float4*>(er + k * C_EDGE + c8);
            const float4 bq = *reinterpret_cast<const float4*>(er + k * C_EDGE + c8 + 4);
            __half2 h0 = __floats2half2_rn(a.x, a.y), h1 = __floats2half2_rn(a.z, a.w);
            __half2 h2 = __floats2half2_rn(bq.x, bq.y), h3 = __floats2half2_rn(bq.z, bq.w);
            w = make_uint4(*(uint32_t*)&h0, *(uint32_t*)&h1, *(uint32_t*)&h2, *(uint32_t*)&h3);
        } else if (c8 < C_EDGE + C_BIAS) {
            w = *reinterpret_cast<const uint4*>(s_self + (c8 - C_EDGE));
        } else {
            const float* src = nb + (size_t)s_idx[k] * C_BIAS + (c8 - C_EDGE - C_BIAS);
            const float4 a = *reinterpret_cast<const float4*>(src);
            const float4 bq = *reinterpret_cast<const float4*>(src + 4);
            __half2 h0 = __floats2half2_rn(a.x, a.y), h1 = __floats2half2_rn(a.z, a.w);
            __half2 h2 = __floats2half2_rn(bq.x, bq.y), h3 = __floats2half2_rn(bq.z, bq.w);
            w = make_uint4(*(uint32_t*)&h0, *(uint32_t*)&h1, *(uint32_t*)&h2, *(uint32_t*)&h3);
        }
        *reinterpret_cast<uint4*>(xr + k * HID + c8) = w;
    }
}

// ---------------------------------------------------------------------------
// GEMM: C[M, Nc] = act( A @ Bw + bias ),  K = KT*64  (lda = 512, ldb = Nc).
// fp16 in / fp32 accumulate, mma.sync m16n8k16.
// BM=128, BN=128, BK=64; 256 threads (8 warps 4x2), warp tile 32x64.
// 3-stage cp.async pipeline, ONE __syncthreads per K-tile.
// Dual-A: k-tiles >= 8 read A1 (residual by linearity).
// LN_OUT: stage acc+bias to smem, fused LayerNorm epilogue (Nc must be 128).
// ---------------------------------------------------------------------------
template <bool RELU, bool LN_OUT>
__global__ void __launch_bounds__(256, 2)
gemm_kernel(const __half* __restrict__ A0, const __half* __restrict__ A1,
            const __half* __restrict__ Bw, const float* __restrict__ bias,
            const float* __restrict__ gamma, const float* __restrict__ beta,
            __half* __restrict__ Ch, float* __restrict__ Cf,
            int Nc, int KT) {
    constexpr int BM = 128, BN = 128, BK = 64;
    constexpr int LDA = BK + 8;   // 72
    constexpr int LDB = BN + 8;   // 136
    extern __shared__ __align__(16) char smem_raw[];
    __half (*As)[BM][LDA] = reinterpret_cast<__half (*)[BM][LDA]>(smem_raw);
    __half (*Bs)[BK][LDB] = reinterpret_cast<__half (*)[BK][LDB]>(smem_raw + 3 * BM * LDA * 2);

    const int t = threadIdx.x, lane = t & 31, wid = t >> 5;
    const int bm = blockIdx.y, bn = blockIdx.x;
    const int wm = (wid >> 1) * 32, wn = (wid & 1) * 64;

    float acc[2][8][4];
#pragma unroll
    for (int a = 0; a < 2; a++)
#pragma unroll
        for (int b = 0; b < 8; b++)
#pragma unroll
            for (int c = 0; c < 4; c++) acc[a][b][c] = 0.f;

    auto load_tiles = [&](int st, int kt) {
        const __half* Ab = (kt >= 8) ? A1 : A0;
        const int k0 = (kt & 7) * BK;
#pragma unroll
        for (int j = 0; j < 4; j++) {                 // A: 128 rows x 64 cols, 1024 segs
            const int idx = j * 256 + t;
            const int r = idx >> 3, sg = idx & 7;
            const __half* src = Ab + ((size_t)bm * BM + r) * HID + k0 + sg * 8;
            const uint32_t dst = (uint32_t)__cvta_generic_to_shared(&As[st][r][sg * 8]);
            asm volatile("cp.async.cg.shared.global [%0], [%1], 16;\n" :: "r"(dst), "l"(src));
        }
#pragma unroll
        for (int j = 0; j < 4; j++) {                 // B: 64 rows x 128 cols, 1024 segs
            const int idx = j * 256 + t;
            const int r = idx >> 4, sg = idx & 15;
            const __half* src = Bw + (size_t)(k0 + r) * Nc + bn * BN + sg * 8;
            const uint32_t dst = (uint32_t)__cvta_generic_to_shared(&Bs[st][r][sg * 8]);
            asm volatile("cp.async.cg.shared.global [%0], [%1], 16;\n" :: "r"(dst), "l"(src));
        }
    };

    load_tiles(0, 0);
    asm volatile("cp.async.commit_group;\n");
    if (KT > 1) {
        load_tiles(1, 1);
        asm volatile("cp.async.commit_group;\n");
    }

    int st = 0;
    for (int kt = 0; kt < KT; kt++, st = (st == 2) ? 0 : st + 1) {
        if (kt < KT - 1) asm volatile("cp.async.wait_group 1;\n");
        else             asm volatile("cp.async.wait_group 0;\n");
        __syncthreads();
        if (kt + 2 < KT) {
            const int st2 = (st + 2 > 2) ? st - 1 : st + 2;
            load_tiles(st2, kt + 2);
            asm volatile("cp.async.commit_group;\n");
        }
#pragma unroll
        for (int kk = 0; kk < 4; kk++) {
            uint32_t afr[2][4];
#pragma unroll
            for (int mi = 0; mi < 2; mi++) {
                const uint32_t addr = (uint32_t)__cvta_generic_to_shared(
                    &As[st][wm + mi * 16 + (lane & 15)][kk * 16 + ((lane >> 4) << 3)]);
                asm volatile("ldmatrix.sync.aligned.m8n8.x4.shared.b16 {%0,%1,%2,%3}, [%4];\n"
                             : "=r"(afr[mi][0]), "=r"(afr[mi][1]), "=r"(afr[mi][2]), "=r"(afr[mi][3])
                             : "r"(addr));
            }
            uint32_t bfr[4][4];
#pragma unroll
            for (int nj = 0; nj < 4; nj++) {
                const uint32_t addr = (uint32_t)__cvta_generic_to_shared(
                    &Bs[st][kk * 16 + (lane & 15)][wn + nj * 16 + ((lane >> 4) << 3)]);
                asm volatile("ldmatrix.sync.aligned.m8n8.x4.trans.shared.b16 {%0,%1,%2,%3}, [%4];\n"
                             : "=r"(bfr[nj][0]), "=r"(bfr[nj][1]), "=r"(bfr[nj][2]), "=r"(bfr[nj][3])
                             : "r"(addr));
            }
#pragma unroll
            for (int mi = 0; mi < 2; mi++)
#pragma unroll
                for (int n8 = 0; n8 < 8; n8++) {
                    const uint32_t b0 = bfr[n8 >> 1][(n8 & 1) * 2 + 0];
                    const uint32_t b1 = bfr[n8 >> 1][(n8 & 1) * 2 + 1];
                    asm volatile(
                        "mma.sync.aligned.m16n8k16.row.col.f32.f16.f16.f32 "
                        "{%0,%1,%2,%3}, {%4,%5,%6,%7}, {%8,%9}, {%0,%1,%2,%3};\n"
                        : "+f"(acc[mi][n8][0]), "+f"(acc[mi][n8][1]),
                          "+f"(acc[mi][n8][2]), "+f"(acc[mi][n8][3])
                        : "r"(afr[mi][0]), "r"(afr[mi][1]), "r"(afr[mi][2]), "r"(afr[mi][3]),
                          "r"(b0), "r"(b1));
                }
        }
    }

    const int lr = lane >> 2, lc = (lane & 3) * 2;
    if (!LN_OUT) {
        // +bias, optional relu, fp16 store
#pragma unroll
        for (int mi = 0; mi < 2; mi++) {
#pragma unroll
            for (int n8 = 0; n8 < 8; n8++) {
                const int row = bm * BM + wm + mi * 16 + lr;
                const int col = bn * BN + wn + n8 * 8 + lc;
                const float bv0 = bias[col], bv1 = bias[col + 1];
                float v0 = acc[mi][n8][0] + bv0;
                float v1 = acc[mi][n8][1] + bv1;
                float v2 = acc[mi][n8][2] + bv0;
                float v3 = acc[mi][n8][3] + bv1;
                if (RELU) {
                    v0 = fmaxf(v0, 0.f); v1 = fmaxf(v1, 0.f);
                    v2 = fmaxf(v2, 0.f); v3 = fmaxf(v3, 0.f);
                }
                *reinterpret_cast<__half2*>(Ch + (size_t)row * Nc + col)       = __floats2half2_rn(v0, v1);
                *reinterpret_cast<__half2*>(Ch + (size_t)(row + 8) * Nc + col) = __floats2half2_rn(v2, v3);
            }
        }
    } else {
        // stage acc+bias to smem, then fused LayerNorm (Nc == 128, bn == 0)
        constexpr int LDY = 132;
        float* sY = reinterpret_cast<float*>(smem_raw);
        __syncthreads();          // all ldmatrix reads of As/Bs done before reuse
#pragma unroll
        for (int mi = 0; mi < 2; mi++) {
#pragma unroll
            for (int n8 = 0; n8 < 8; n8++) {
                const int r = wm + mi * 16 + lr;
                const int c = wn + n8 * 8 + lc;
                const float bv0 = bias[c], bv1 = bias[c + 1];
                *reinterpret_cast<float2*>(&sY[r * LDY + c]) =
                    make_float2(acc[mi][n8][0] + bv0, acc[mi][n8][1] + bv1);
                *reinterpret_cast<float2*>(&sY[(r + 8) * LDY + c]) =
                    make_float2(acc[mi][n8][2] + bv0, acc[mi][n8][3] + bv1);
            }
        }
        __syncthreads();
        const float4 gg = reinterpret_cast<const float4*>(gamma)[lane];
        const float4 bb = reinterpret_cast<const float4*>(beta)[lane];
#pragma unroll
        for (int rr = 0; rr < 16; rr++) {
            const int r = wid * 16 + rr;
            const float4 v = *reinterpret_cast<const float4*>(&sY[r * LDY + lane * 4]);
            float s  = v.x + v.y + v.z + v.w;
            float sq = v.x * v.x + v.y * v.y + v.z * v.z + v.w * v.w;
#pragma unroll
            for (int off = 16; off > 0; off >>= 1) {
                s  += __shfl_xor_sync(0xffffffffu, s, off);
                sq += __shfl_xor_sync(0xffffffffu, sq, off);
            }
            const float mu  = s * (1.f / 128.f);
            const float inv = rsqrtf(sq * (1.f / 128.f) - mu * mu + 1e-5f);
            float4 o;
            o.x = (v.x - mu) * inv * gg.x + bb.x;
            o.y = (v.y - mu) * inv * gg.y + bb.y;
            o.z = (v.z - mu) * inv * gg.z + bb.z;
            o.w = (v.w - mu) * inv * gg.w + bb.w;
            *reinterpret_cast<float4*>(Cf + (size_t)(bm * BM + r) * 128 + lane * 4) = o;
        }
    }
}

// ---------------------------------------------------------------------------
// Launch
// ---------------------------------------------------------------------------
extern "C" void kernel_launch(void* const* d_in, const int* in_sizes, int n_in,
                              void* d_out, int out_size) {
    const float* node  = (const float*)d_in[0];
    const float* edge  = (const float*)d_in[1];
    const int*   eidx  = (const int*)  d_in[2];
    const float* Wi    = (const float*)d_in[3];
    const float* bi    = (const float*)d_in[4];
    const float* W1    = (const float*)d_in[5];
    const float* b1    = (const float*)d_in[6];
    const float* W2    = (const float*)d_in[7];
    const float* b2    = (const float*)d_in[8];
    const float* Wf    = (const float*)d_in[9];
    const float* bf    = (const float*)d_in[10];
    const float* gamma = (const float*)d_in[11];
    const float* beta  = (const float*)d_in[12];
    float* out = (float*)d_out;

    void *pW1h, *pW2h, *pWfh, *pX, *pH, *pH2;
    cudaGetSymbolAddress(&pW1h, g_W1h);
    cudaGetSymbolAddress(&pW2h, g_W2h);
    cudaGetSymbolAddress(&pWfh, g_Wfh);
    cudaGetSymbolAddress(&pX,  g_X);
    cudaGetSymbolAddress(&pH,  g_H);
    cudaGetSymbolAddress(&pH2, g_H2);

    // dynamic smem: 3 stages of (As 128x72 + Bs 64x136) fp16
    const int SMEM = 3 * (128 * 72 + 64 * 136) * 2;   // 107,520 B
    cudaFuncSetAttribute(gemm_kernel<true,  false>,
                         cudaFuncAttributeMaxDynamicSharedMemorySize, SMEM);
    cudaFuncSetAttribute(gemm_kernel<false, true>,
                         cudaFuncAttributeMaxDynamicSharedMemorySize, SMEM);

    f2h_kernel<<<512, 256>>>(W1, (__half*)pW1h, HID * HID);      // launch 0
    f2h_kernel<<<512, 256>>>(W2, (__half*)pW2h, HID * HID);      // launch 1
    f2h_kernel<<<256, 256>>>(Wf, (__half*)pWfh, HID * C_OUT_);   // launch 2

    node_proj_kernel<<<NODES / 2, 2 * C_BIAS>>>(node, Wi, bi);   // launch 3
    build_x_kernel<<<NODES, 256>>>(edge, eidx);                  // launch 4

    // h = relu(X @ W1 + b1)                                        launch 5
    gemm_kernel<true, false><<<dim3(HID / 128, MROWS / 128), 256, SMEM>>>(
        (const __half*)pX, (const __half*)pX, (const __half*)pW1h, b1,
        nullptr, nullptr, (__half*)pH, nullptr, HID, 8);
    // h2 = relu(h @ W2 + b2)                                       launch 6
    gemm_kernel<true, false><<<dim3(HID / 128, MROWS / 128), 256, SMEM>>>(
        (const __half*)pH, (const __half*)pH, (const __half*)pW2h, b2,
        nullptr, nullptr, (__half*)pH2, nullptr, HID, 8);
    // out = LN((h2 + X) @ Wf + bf)   (dual-A K=1024, fused LN)     launch 7
    gemm_kernel<false, true><<<dim3(1, MROWS / 128), 256, SMEM>>>(
        (const __half*)pH2, (const __half*)pX, (const __half*)pWfh, bf,
        gamma, beta, nullptr, out, C_OUT_, 16);
}